// round 1
// baseline (speedup 1.0000x reference)
#include <cuda_runtime.h>
#include <cstdint>

// Problem constants
#define NB   32
#define IC   64
#define OCH  128
#define HH   128
#define WW   128
#define OH   126
#define OW   126

// Tiling
#define TILE_OW 16
#define TILE_OH 8
#define ICC     8                 // ic chunk in smem
#define NCHUNK  (IC / ICC)        // 8
#define IN_H    (TILE_OH + 2)     // 10
#define IN_W    (TILE_OW + 2)     // 18
#define IN_WS   20                // padded row stride (keeps float4 alignment)
#define WPAD    12                // padded weight stride (16B-aligned LDS.128)
#define OC_BLK  64
#define OC_T    4                 // oc per thread

// ---- f32x2 packed helpers (sm_103a FFMA2 — PTX-only path) ----
__device__ __forceinline__ unsigned long long pk2(float lo, float hi) {
    unsigned long long r;
    asm("mov.b64 %0, {%1, %2};" : "=l"(r) : "f"(lo), "f"(hi));
    return r;
}
__device__ __forceinline__ unsigned long long ffma2(unsigned long long a,
                                                    unsigned long long b,
                                                    unsigned long long c) {
    unsigned long long d;
    asm("fma.rn.f32x2 %0, %1, %2, %3;" : "=l"(d) : "l"(a), "l"(b), "l"(c));
    return d;
}

__global__ void __launch_bounds__(256, 2)
conv_mish_kernel(const float* __restrict__ x,
                 const float* __restrict__ wg,
                 const float* __restrict__ bias,
                 float* __restrict__ out)
{
    __shared__ float s_in[ICC][IN_H][IN_WS];     // 6400 B
    __shared__ float s_w[ICC][OC_BLK][WPAD];     // 24576 B

    const int tid  = threadIdx.x;
    const int ow_t = tid & 3;            // 4 positions * 4 ow each = 16 ow
    const int oh_t = (tid >> 2) & 3;     // 4 positions * 2 oh each = 8 oh
    const int oc_t = tid >> 4;           // 16 positions * 4 oc each = 64 oc

    const int ow0 = blockIdx.x * TILE_OW;
    const int oh0 = blockIdx.y * TILE_OH;
    const int n   = blockIdx.z >> 1;
    const int ocg = blockIdx.z & 1;

    const int ow_base = ow_t * 4;        // local ow start for this thread
    const int oh_base = oh_t * 2;        // local oh start for this thread

    // acc[oc][ohl][owpair] : each holds 2 adjacent-ow fp32 outputs
    unsigned long long acc[OC_T][2][2];
    #pragma unroll
    for (int a = 0; a < OC_T; a++)
        #pragma unroll
        for (int b = 0; b < 2; b++)
            #pragma unroll
            for (int c = 0; c < 2; c++)
                acc[a][b][c] = 0ull;     // bit pattern of {0.f, 0.f}

    for (int chunk = 0; chunk < NCHUNK; chunk++) {
        const int icb = chunk * ICC;
        __syncthreads();

        // ---- stage input tile: [ICC][IN_H][IN_W], zero-padded at bottom/right edges
        for (int i = tid; i < ICC * IN_H * IN_W; i += 256) {
            int ic  = i / (IN_H * IN_W);
            int rem = i - ic * (IN_H * IN_W);
            int r   = rem / IN_W;
            int c   = rem - r * IN_W;
            int ih  = oh0 + r;
            int iw  = ow0 + c;
            float v = 0.f;
            if (ih < HH && iw < WW)
                v = x[(((n * IC) + icb + ic) * HH + ih) * WW + iw];
            s_in[ic][r][c] = v;
        }
        // ---- stage weights: s_w[icl][oc][k] = wg[ocg*64+oc][icb+icl][k]
        for (int i = tid; i < ICC * OC_BLK * 9; i += 256) {
            int oc  = i / (ICC * 9);
            int rem = i - oc * (ICC * 9);
            int icl = rem / 9;
            int k   = rem - icl * 9;
            s_w[icl][oc][k] = wg[(((ocg * OC_BLK + oc) * IC) + icb + icl) * 9 + k];
        }
        __syncthreads();

        #pragma unroll
        for (int ic = 0; ic < ICC; ic++) {
            // Build 20 packed input pairs: 4 rows x 5 overlapping (w,w+1) pairs
            unsigned long long p[4][5];
            #pragma unroll
            for (int rr = 0; rr < 4; rr++) {
                const float* rp = &s_in[ic][oh_base + rr][ow_base];
                float4 a = *(const float4*)rp;          // 16B aligned
                float2 b = *(const float2*)(rp + 4);    // 8B aligned
                float xv[6] = {a.x, a.y, a.z, a.w, b.x, b.y};
                #pragma unroll
                for (int i2 = 0; i2 < 5; i2++)
                    p[rr][i2] = pk2(xv[i2], xv[i2 + 1]);
            }

            #pragma unroll
            for (int oc = 0; oc < OC_T; oc++) {
                const float* wp = &s_w[ic][oc_t * OC_T + oc][0];
                float4 w0 = *(const float4*)wp;         // 16B aligned (WPAD=12)
                float4 w1 = *(const float4*)(wp + 4);
                float  w8 = wp[8];
                float wk[9] = {w0.x, w0.y, w0.z, w0.w, w1.x, w1.y, w1.z, w1.w, w8};

                #pragma unroll
                for (int kh = 0; kh < 3; kh++)
                    #pragma unroll
                    for (int kw = 0; kw < 3; kw++) {
                        unsigned long long wpk = pk2(wk[kh * 3 + kw], wk[kh * 3 + kw]);
                        #pragma unroll
                        for (int ohl = 0; ohl < 2; ohl++)
                            #pragma unroll
                            for (int owp = 0; owp < 2; owp++)
                                acc[oc][ohl][owp] =
                                    ffma2(p[ohl + kh][owp * 2 + kw], wpk,
                                          acc[oc][ohl][owp]);
                    }
            }
        }
    }

    // ---- epilogue: bias, subtract 0.7, Mish = v * (s-1)/(s+1), s = (1+e^v)^2
    #pragma unroll
    for (int oc = 0; oc < OC_T; oc++) {
        const int ocG = ocg * OC_BLK + oc_t * OC_T + oc;
        const float bv = bias[ocG] - 0.7f;   // SUB1 + SUB2 = 0.5 + 0.2
        #pragma unroll
        for (int ohl = 0; ohl < 2; ohl++) {
            const int oh = oh0 + oh_base + ohl;
            if (oh >= OH) continue;
            #pragma unroll
            for (int owp = 0; owp < 2; owp++) {
                const unsigned long long a = acc[oc][ohl][owp];
                float vs[2];
                vs[0] = __uint_as_float((unsigned)(a & 0xffffffffull));
                vs[1] = __uint_as_float((unsigned)(a >> 32));
                #pragma unroll
                for (int hf = 0; hf < 2; hf++) {
                    const int ow = ow0 + ow_base + owp * 2 + hf;
                    if (ow >= OW) continue;
                    float v = vs[hf] + bv;
                    // mish(v) = v * tanh(log1p(exp(v))) = v * (s-1)/(s+1), s=(1+e^v)^2
                    float t = __expf(fminf(v, 15.f));   // clamp: v>15 -> tanh==1 to fp32
                    float s = 1.f + t;
                    s = s * s;
                    out[((n * OCH + ocG) * OH + oh) * OW + ow] =
                        v * (s - 1.f) / (s + 1.f);
                }
            }
        }
    }
}

extern "C" void kernel_launch(void* const* d_in, const int* in_sizes, int n_in,
                              void* d_out, int out_size) {
    const float* x  = (const float*)d_in[0];
    const float* w  = (const float*)d_in[1];
    const float* b  = (const float*)d_in[2];
    float* out      = (float*)d_out;

    dim3 grid((OW + TILE_OW - 1) / TILE_OW,    // 8
              (OH + TILE_OH - 1) / TILE_OH,    // 16
              NB * 2);                          // batch x oc-group
    conv_mish_kernel<<<grid, 256>>>(x, w, b, out);
}

// round 2
// speedup vs baseline: 1.2094x; 1.2094x over previous
#include <cuda_runtime.h>
#include <cstdint>

// Problem constants
#define NB   32
#define IC   64
#define OCH  128
#define HH   128
#define WW   128
#define OH   126
#define OW   126

// Tiling
#define ICC     8                 // ic chunk staged in smem
#define NCHUNK  (IC / ICC)        // 8
#define TILE_OH 6                 // oh per CTA (21 blocks * 6 = 126 exact)
#define IN_H    (TILE_OH + 2)     // 8 input rows
#define IN_W    130               // 128 ow lanes + 2 halo
#define OC_CTA  16                // oc per CTA
#define OCP     8                 // oc-pairs per thread (all 16 oc)
#define OH_T    3                 // oh per thread

// dynamic smem layout:
//   ull   s_in[ICC][IN_H][IN_W]   duplicated {v,v} pairs  (66560 B)
//   float s_w [ICC][9][OC_CTA]    transposed weights      ( 4608 B)
#define S_IN_ELEMS (ICC * IN_H * IN_W)
#define SMEM_BYTES (S_IN_ELEMS * 8 + ICC * 9 * OC_CTA * 4)

typedef unsigned long long ull;

__device__ __forceinline__ ull ffma2(ull a, ull b, ull c) {
    ull d;
    asm("fma.rn.f32x2 %0, %1, %2, %3;" : "=l"(d) : "l"(a), "l"(b), "l"(c));
    return d;
}
__device__ __forceinline__ ull dup2(float v) {
    ull r;
    asm("mov.b64 %0, {%1, %1};" : "=l"(r) : "f"(v));
    return r;
}

__global__ void __launch_bounds__(256, 2)
conv_mish_kernel(const float* __restrict__ x,
                 const float* __restrict__ wg,
                 const float* __restrict__ bias,
                 float* __restrict__ out)
{
    extern __shared__ char smem_raw[];
    ull*   s_in = (ull*)smem_raw;                         // [ICC][IN_H][IN_W]
    float* s_w  = (float*)(smem_raw + S_IN_ELEMS * 8);    // [ICC][9][OC_CTA]

    const int tid  = threadIdx.x;
    const int lane = tid & 31;
    const int warp = tid >> 5;
    const int warp_ow = warp & 3;        // 4 warps span 128 ow
    const int warp_oh = warp >> 2;       // 2 warps span 6 oh (3 each)

    const int ow_lane = warp_ow * 32 + lane;   // 0..127
    const int oh_base = warp_oh * OH_T;        // 0 or 3

    const int ocg = blockIdx.x;          // 0..7 : oc group of 16
    const int oh0 = blockIdx.y * TILE_OH;
    const int n   = blockIdx.z;

    // acc[p][ohl] = packed outputs for oc = ocg*16 + 2p, 2p+1
    ull acc[OCP][OH_T];
    #pragma unroll
    for (int p = 0; p < OCP; p++)
        #pragma unroll
        for (int r = 0; r < OH_T; r++)
            acc[p][r] = 0ull;

    for (int chunk = 0; chunk < NCHUNK; chunk++) {
        const int icb = chunk * ICC;
        __syncthreads();

        // ---- stage duplicated input tile: s_in[ic][r][w] = {x, x}
        for (int i = tid; i < S_IN_ELEMS; i += 256) {
            int w    = i % IN_W;
            int rest = i / IN_W;
            int r    = rest % IN_H;
            int icl  = rest / IN_H;
            float v = 0.f;
            if (w < WW)
                v = x[(((n * IC) + icb + icl) * HH + (oh0 + r)) * WW + w];
            s_in[i] = dup2(v);
        }
        // ---- stage transposed weights: s_w[icl][k][ocl]
        for (int i = tid; i < ICC * 9 * OC_CTA; i += 256) {
            int ocl = i & (OC_CTA - 1);
            int k   = (i >> 4) % 9;
            int icl = i / (9 * OC_CTA);
            s_w[i] = wg[(((ocg * OC_CTA + ocl) * IC) + icb + icl) * 9 + k];
        }
        __syncthreads();

        #pragma unroll
        for (int icl = 0; icl < ICC; icl++) {
            // 15 broadcast input pairs: rows oh_base..oh_base+4, kw 0..2
            ull inp[OH_T + 2][3];
            #pragma unroll
            for (int r = 0; r < OH_T + 2; r++)
                #pragma unroll
                for (int kw = 0; kw < 3; kw++)
                    inp[r][kw] =
                        s_in[(icl * IN_H + (oh_base + r)) * IN_W + ow_lane + kw];

            #pragma unroll
            for (int k = 0; k < 9; k++) {
                const int kh = k / 3;
                const int kw = k % 3;
                // 16 oc weights for this (ic,k): 4x LDS.128 broadcast
                const ulonglong2* wp =
                    (const ulonglong2*)&s_w[(icl * 9 + k) * OC_CTA];
                ulonglong2 w01 = wp[0];   // pairs p0,p1
                ulonglong2 w23 = wp[1];   // pairs p2,p3
                ulonglong2 w45 = wp[2];   // pairs p4,p5
                ulonglong2 w67 = wp[3];   // pairs p6,p7
                ull wpair[OCP] = {w01.x, w01.y, w23.x, w23.y,
                                  w45.x, w45.y, w67.x, w67.y};
                #pragma unroll
                for (int ohl = 0; ohl < OH_T; ohl++) {
                    ull iv = inp[ohl + kh][kw];
                    #pragma unroll
                    for (int p = 0; p < OCP; p++)
                        acc[p][ohl] = ffma2(iv, wpair[p], acc[p][ohl]);
                }
            }
        }
    }

    // ---- epilogue: bias, subtract 0.7, Mish = v*(s-1)/(s+1), s=(1+e^v)^2
    if (ow_lane < OW) {
        #pragma unroll
        for (int p = 0; p < OCP; p++) {
            const int oc0 = ocg * OC_CTA + 2 * p;
            const float b0 = bias[oc0]     - 0.7f;
            const float b1 = bias[oc0 + 1] - 0.7f;
            #pragma unroll
            for (int ohl = 0; ohl < OH_T; ohl++) {
                const int oh = oh0 + oh_base + ohl;
                const ull a = acc[p][ohl];
                float v0 = __uint_as_float((unsigned)(a & 0xffffffffull)) + b0;
                float v1 = __uint_as_float((unsigned)(a >> 32)) + b1;

                float t0 = __expf(fminf(v0, 15.f));
                float s0 = 1.f + t0; s0 = s0 * s0;
                float t1 = __expf(fminf(v1, 15.f));
                float s1 = 1.f + t1; s1 = s1 * s1;

                const size_t base = ((size_t)(n * OCH + oc0) * OH + oh) * OW + ow_lane;
                out[base]               = v0 * __fdividef(s0 - 1.f, s0 + 1.f);
                out[base + (size_t)OH * OW] = v1 * __fdividef(s1 - 1.f, s1 + 1.f);
            }
        }
    }
}

extern "C" void kernel_launch(void* const* d_in, const int* in_sizes, int n_in,
                              void* d_out, int out_size) {
    const float* x  = (const float*)d_in[0];
    const float* w  = (const float*)d_in[1];
    const float* b  = (const float*)d_in[2];
    float* out      = (float*)d_out;

    cudaFuncSetAttribute(conv_mish_kernel,
                         cudaFuncAttributeMaxDynamicSharedMemorySize,
                         SMEM_BYTES);

    dim3 grid(OCH / OC_CTA,          // 8  (oc groups adjacent -> L2 input reuse)
              OH / TILE_OH,          // 21
              NB);                   // 32
    conv_mish_kernel<<<grid, 256, SMEM_BYTES>>>(x, w, b, out);
}

// round 4
// speedup vs baseline: 5.4034x; 4.4678x over previous
#include <cuda_runtime.h>
#include <cuda_fp16.h>
#include <cstdint>

// ---------------- problem constants ----------------
#define NB   32
#define IC   64
#define OCH  128
#define HH   128
#define WW   128
#define OH   126
#define OW   126

// smem: s_x[w 0..129][ic 0..63] halves, stride 72 ; s_w[oc 0..127][ic], stride 72
#define XSTR   72
#define SX_ROWS 130
#define SX_BYTES (SX_ROWS * XSTR * 2)           // 18720
#define SW_OFF   SX_BYTES
#define SW_BYTES (OCH * XSTR * 2)               // 18432
#define SMEM_BYTES (SX_BYTES + SW_BYTES)        // 37152

// pre-converted fp16 weights: g_wh[kk][oc][ic/2] as half2
__device__ __half2 g_wh[9 * OCH * (IC / 2)];

__global__ void wt_half_kernel(const float* __restrict__ wg) {
    int i = blockIdx.x * 256 + threadIdx.x;          // over 9*128*32
    if (i < 9 * OCH * (IC / 2)) {
        int kk  = i / (OCH * 32);
        int r   = i - kk * (OCH * 32);
        int oc  = r >> 5;
        int ic  = (r & 31) * 2;
        float v0 = wg[(oc * IC + ic)     * 9 + kk];
        float v1 = wg[(oc * IC + ic + 1) * 9 + kk];
        g_wh[i] = __floats2half2_rn(v0, v1);
    }
}

__device__ __forceinline__ void hmma16816(float* c, const uint32_t* a,
                                          const uint32_t* b) {
    asm volatile(
        "mma.sync.aligned.m16n8k16.row.col.f32.f16.f16.f32 "
        "{%0,%1,%2,%3}, {%4,%5,%6,%7}, {%8,%9}, {%0,%1,%2,%3};"
        : "+f"(c[0]), "+f"(c[1]), "+f"(c[2]), "+f"(c[3])
        : "r"(a[0]), "r"(a[1]), "r"(a[2]), "r"(a[3]), "r"(b[0]), "r"(b[1]));
}

__global__ void __launch_bounds__(256, 2)
conv_hmma_kernel(const float* __restrict__ x,
                 const float* __restrict__ bias,
                 float* __restrict__ out)
{
    extern __shared__ char smem[];

    const int tid  = threadIdx.x;
    const int lane = tid & 31;
    const int warp = tid >> 5;
    const int g    = lane >> 2;      // group id 0..7
    const int t    = lane & 3;       // thread in group

    const int warp_m = warp & 1;     // 2 warps over M=128 (64 each)
    const int warp_n = warp >> 1;    // 4 warps over N=128 (32 each)

    const int oh = blockIdx.x;
    const int n  = blockIdx.y;

    float c[4][4][4];                // [m-tile][n-tile][reg]
    #pragma unroll
    for (int i = 0; i < 4; i++)
        #pragma unroll
        for (int j = 0; j < 4; j++)
            #pragma unroll
            for (int r = 0; r < 4; r++)
                c[i][j][r] = 0.f;

    const uint32_t* gwu = (const uint32_t*)g_wh;

    for (int kh = 0; kh < 3; kh++) {
        const int ih = oh + kh;
        __syncthreads();   // all compute on previous s_x finished

        // ---- stage s_x[w][ic] (fp16) from x row ih, 64 ic, w 0..129
        {
            const float* xbase = x + ((size_t)n * IC * HH + ih) * WW;
            for (int idx = tid; idx < IC * SX_ROWS; idx += 256) {
                int ic = idx / SX_ROWS;
                int w  = idx - ic * SX_ROWS;
                float v = (w < WW) ? xbase[(size_t)ic * (HH * WW) + w] : 0.f;
                *(__half*)(smem + (w * XSTR + ic) * 2) = __float2half_rn(v);
            }
        }

        for (int kw = 0; kw < 3; kw++) {
            const int kk = kh * 3 + kw;
            __syncthreads();   // prev compute done (s_w reuse) / s_x visible

            // ---- stage s_w[oc][ic] from g_wh[kk]
            {
                const uint32_t* gw = gwu + kk * (OCH * 32);
                #pragma unroll
                for (int i = 0; i < 16; i++) {
                    int idx = tid + i * 256;       // 4096 half2
                    int oc  = idx >> 5;
                    int icp = idx & 31;
                    *(uint32_t*)(smem + SW_OFF + oc * (XSTR * 2) + icp * 4) =
                        gw[idx];
                }
            }
            __syncthreads();

            // ---- 4 k-steps of 16
            #pragma unroll
            for (int ks = 0; ks < 4; ks++) {
                const int k0 = ks * 16;

                uint32_t a[4][4];
                #pragma unroll
                for (int i = 0; i < 4; i++) {
                    const int row = warp_m * 64 + i * 16 + g + kw;
                    const int base = (row * XSTR + k0 + 2 * t) * 2;
                    a[i][0] = *(const uint32_t*)(smem + base);
                    a[i][1] = *(const uint32_t*)(smem + base + 8 * XSTR * 2);
                    a[i][2] = *(const uint32_t*)(smem + base + 16);
                    a[i][3] = *(const uint32_t*)(smem + base + 8 * XSTR * 2 + 16);
                }
                #pragma unroll
                for (int j = 0; j < 4; j++) {
                    const int nrow = warp_n * 32 + j * 8 + g;
                    const int base = SW_OFF + (nrow * XSTR + k0 + 2 * t) * 2;
                    uint32_t b[2];
                    b[0] = *(const uint32_t*)(smem + base);
                    b[1] = *(const uint32_t*)(smem + base + 16);
                    #pragma unroll
                    for (int i = 0; i < 4; i++)
                        hmma16816(c[i][j], a[i], b);
                }
            }
        }
    }

    // ---- epilogue: bias, -0.7, Mish ----
    #pragma unroll
    for (int j = 0; j < 4; j++) {
        const int oc0 = warp_n * 32 + j * 8 + 2 * t;
        const float b0 = bias[oc0]     - 0.7f;
        const float b1 = bias[oc0 + 1] - 0.7f;
        #pragma unroll
        for (int i = 0; i < 4; i++) {
            #pragma unroll
            for (int r = 0; r < 4; r++) {
                const int m  = warp_m * 64 + i * 16 + g + ((r & 2) ? 8 : 0);
                if (m >= OW) continue;
                const int oc = oc0 + (r & 1);
                float v = c[i][j][r] + ((r & 1) ? b1 : b0);
                float e = __expf(fminf(v, 15.f));
                float s = 1.f + e; s = s * s;
                out[((size_t)(n * OCH + oc) * OH + oh) * OW + m] =
                    v * __fdividef(s - 1.f, s + 1.f);
            }
        }
    }
}

extern "C" void kernel_launch(void* const* d_in, const int* in_sizes, int n_in,
                              void* d_out, int out_size) {
    const float* x  = (const float*)d_in[0];
    const float* w  = (const float*)d_in[1];
    const float* b  = (const float*)d_in[2];
    float* out      = (float*)d_out;

    wt_half_kernel<<<(9 * OCH * (IC / 2) + 255) / 256, 256>>>(w);

    dim3 grid(OH, NB);   // 126 x 32 CTAs, one (n, oh) each
    conv_hmma_kernel<<<grid, 256, SMEM_BYTES>>>(x, b, out);
}

// round 5
// speedup vs baseline: 8.6637x; 1.6034x over previous
#include <cuda_runtime.h>
#include <cuda_fp16.h>
#include <cstdint>

// ---------------- problem constants ----------------
#define NB   32
#define IC   64
#define OCH  128
#define HH   128
#define WW   128
#define OH   126
#define OW   126

// smem: s_x[w 0..129][ic 0..63] halves, stride XSTR ; s_w3[kw][oc][ic] stride XSTR
#define XSTR     72
#define SX_ROWS  130
#define SX_BYTES (SX_ROWS * XSTR * 2)            // 18720
#define SW_OFF   SX_BYTES
#define TAPB     (OCH * XSTR * 2)                // 18432 per tap
#define SMEM_BYTES (SX_BYTES + 3 * TAPB)         // 74016

// pre-converted fp16 weights: g_wh[kk][oc][ic/2] as half2 (row = oc, 64 halves)
__device__ __half2 g_wh[9 * OCH * (IC / 2)];

__global__ void wt_half_kernel(const float* __restrict__ wg) {
    int i = blockIdx.x * 256 + threadIdx.x;          // over 9*128*32
    if (i < 9 * OCH * (IC / 2)) {
        int kk  = i / (OCH * 32);
        int r   = i - kk * (OCH * 32);
        int oc  = r >> 5;
        int ic  = (r & 31) * 2;
        float v0 = wg[(oc * IC + ic)     * 9 + kk];
        float v1 = wg[(oc * IC + ic + 1) * 9 + kk];
        g_wh[i] = __floats2half2_rn(v0, v1);
    }
}

__device__ __forceinline__ uint32_t smem_u32(const void* p) {
    uint32_t a;
    asm("{ .reg .u64 t; cvta.to.shared.u64 t, %1; cvt.u32.u64 %0, t; }"
        : "=r"(a) : "l"(p));
    return a;
}

__device__ __forceinline__ void ldsm_x4(uint32_t& r0, uint32_t& r1,
                                        uint32_t& r2, uint32_t& r3,
                                        uint32_t addr) {
    asm volatile("ldmatrix.sync.aligned.m8n8.x4.shared.b16 {%0,%1,%2,%3}, [%4];"
                 : "=r"(r0), "=r"(r1), "=r"(r2), "=r"(r3) : "r"(addr));
}

__device__ __forceinline__ void hmma16816(float* c, const uint32_t* a,
                                          uint32_t b0, uint32_t b1) {
    asm volatile(
        "mma.sync.aligned.m16n8k16.row.col.f32.f16.f16.f32 "
        "{%0,%1,%2,%3}, {%4,%5,%6,%7}, {%8,%9}, {%0,%1,%2,%3};"
        : "+f"(c[0]), "+f"(c[1]), "+f"(c[2]), "+f"(c[3])
        : "r"(a[0]), "r"(a[1]), "r"(a[2]), "r"(a[3]), "r"(b0), "r"(b1));
}

__global__ void __launch_bounds__(256, 2)
conv_hmma_kernel(const float* __restrict__ x,
                 const float* __restrict__ bias,
                 float* __restrict__ out)
{
    extern __shared__ char smem[];
    const uint32_t sbase = smem_u32(smem);

    const int tid  = threadIdx.x;
    const int lane = tid & 31;
    const int warp = tid >> 5;
    const int g    = lane >> 2;      // group id 0..7
    const int t    = lane & 3;       // thread in group

    const int warp_m = warp & 1;     // 2 warps over M=128 (64 each)
    const int warp_n = warp >> 1;    // 4 warps over N=128 (32 each)

    const int oh = blockIdx.x;
    const int n  = blockIdx.y;

    float c[4][4][4];                // [m-tile][n-tile][reg]
    #pragma unroll
    for (int i = 0; i < 4; i++)
        #pragma unroll
        for (int j = 0; j < 4; j++)
            #pragma unroll
            for (int r = 0; r < 4; r++)
                c[i][j][r] = 0.f;

    // ldmatrix per-lane invariant offsets (bytes)
    const int l7 = lane & 7;
    const uint32_t a_lane =
        (uint32_t)(((l7 + ((lane >> 3) & 1) * 8) * XSTR + ((lane >> 4) & 1) * 8) * 2);
    const uint32_t b_lane =
        (uint32_t)(((l7 + ((lane >> 4) & 1) * 8) * XSTR + ((lane >> 3) & 1) * 8) * 2);

    const uint32_t aBase = sbase + a_lane + (uint32_t)(warp_m * 64 * XSTR * 2);
    const uint32_t bBase = sbase + SW_OFF + b_lane + (uint32_t)(warp_n * 32 * XSTR * 2);

    for (int kh = 0; kh < 3; kh++) {
        const int ih = oh + kh;
        __syncthreads();   // previous mainloop done before overwrite

        // ---- stage s_x[w][ic]: warp handles 8 ic rows, lanes = consecutive w
        {
            const float* xbase = x + ((size_t)n * IC * HH + ih) * WW;
            for (int ic = warp; ic < IC; ic += 8) {
                const float* src = xbase + (size_t)ic * (HH * WW);
                #pragma unroll
                for (int cchunk = 0; cchunk < 4; cchunk++) {
                    int w = cchunk * 32 + lane;
                    *(__half*)(smem + (w * XSTR + ic) * 2) =
                        __float2half_rn(src[w]);
                }
                if (lane < 2)   // halo w = 128,129 -> zero
                    *(__half*)(smem + ((128 + lane) * XSTR + ic) * 2) = __half(0.f);
            }
        }
        // ---- stage s_w3: 3 taps of this kh, 16B chunks
        {
            const uint4* gw = (const uint4*)(g_wh + (size_t)(kh * 3) * (OCH * 32));
            #pragma unroll
            for (int it = 0; it < 12; it++) {
                int idx = tid + it * 256;            // 0..3071
                int kwi = idx >> 10;                 // /1024
                int rem = idx & 1023;                // oc*8 + ch
                int oc  = rem >> 3;
                int ch  = rem & 7;
                *(uint4*)(smem + SW_OFF + kwi * TAPB + oc * (XSTR * 2) + ch * 16) =
                    gw[idx];
            }
        }
        __syncthreads();

        #pragma unroll
        for (int kw = 0; kw < 3; kw++) {
            #pragma unroll
            for (int ks = 0; ks < 4; ks++) {
                uint32_t a[4][4];
                #pragma unroll
                for (int i = 0; i < 4; i++)
                    ldsm_x4(a[i][0], a[i][1], a[i][2], a[i][3],
                            aBase + (uint32_t)(((i * 16 + kw) * XSTR + ks * 16) * 2));

                #pragma unroll
                for (int jp = 0; jp < 2; jp++) {
                    uint32_t b0, b1, b2, b3;
                    ldsm_x4(b0, b1, b2, b3,
                            bBase + (uint32_t)(kw * TAPB +
                                     (jp * 16 * XSTR + ks * 16) * 2));
                    #pragma unroll
                    for (int i = 0; i < 4; i++) {
                        hmma16816(c[i][jp * 2],     a[i], b0, b1);
                        hmma16816(c[i][jp * 2 + 1], a[i], b2, b3);
                    }
                }
            }
        }
    }

    // ---- epilogue: bias, -0.7, Mish ----
    #pragma unroll
    for (int j = 0; j < 4; j++) {
        const int oc0 = warp_n * 32 + j * 8 + 2 * t;
        const float b0 = bias[oc0]     - 0.7f;
        const float b1 = bias[oc0 + 1] - 0.7f;
        #pragma unroll
        for (int i = 0; i < 4; i++) {
            #pragma unroll
            for (int r = 0; r < 4; r++) {
                const int m  = warp_m * 64 + i * 16 + g + ((r & 2) ? 8 : 0);
                if (m >= OW) continue;
                const int oc = oc0 + (r & 1);
                float v = c[i][j][r] + ((r & 1) ? b1 : b0);
                float e = __expf(fminf(v, 15.f));
                float s = 1.f + e; s = s * s;
                out[((size_t)(n * OCH + oc) * OH + oh) * OW + m] =
                    v * __fdividef(s - 1.f, s + 1.f);
            }
        }
    }
}

extern "C" void kernel_launch(void* const* d_in, const int* in_sizes, int n_in,
                              void* d_out, int out_size) {
    const float* x  = (const float*)d_in[0];
    const float* w  = (const float*)d_in[1];
    const float* b  = (const float*)d_in[2];
    float* out      = (float*)d_out;

    wt_half_kernel<<<(9 * OCH * (IC / 2) + 255) / 256, 256>>>(w);

    cudaFuncSetAttribute(conv_hmma_kernel,
                         cudaFuncAttributeMaxDynamicSharedMemorySize, SMEM_BYTES);
    dim3 grid(OH, NB);   // 126 x 32 CTAs, one (n, oh) each
    conv_hmma_kernel<<<grid, 256, SMEM_BYTES>>>(x, b, out);
}